// round 1
// baseline (speedup 1.0000x reference)
#include <cuda_runtime.h>

#define BB 4
#define CC 64
#define HH 128
#define WW 416
#define HW (HH*WW)
#define CHW (CC*HH*WW)

// Scratch for warped x2 (no cudaMalloc allowed)
__device__ float g_x2w[(size_t)BB*CHW];

__device__ __forceinline__ float lrelu(float v) { return v >= 0.f ? v : 0.1f*v; }

// ---------------------------------------------------------------------------
// Kernel 1: bilinear warp of x2 by flow -> g_x2w  (zeros outside)
// ---------------------------------------------------------------------------
__global__ void warp_kernel(const float* __restrict__ x2,
                            const float* __restrict__ flow) {
    const int x = blockIdx.x*32 + threadIdx.x;
    const int y = blockIdx.y;
    const int b = blockIdx.z;

    const float fx = flow[((size_t)(b*2+0)*HH + y)*WW + x];
    const float fy = flow[((size_t)(b*2+1)*HH + y)*WW + x];
    const float gx = (float)x + fx;
    const float gy = (float)y + fy;
    const float x0f = floorf(gx), y0f = floorf(gy);
    const float wx = gx - x0f, wy = gy - y0f;
    const int x0 = (int)x0f, y0 = (int)y0f;
    const int x1i = x0 + 1,  y1i = y0 + 1;

    const float vx0 = (x0  >= 0 && x0  < WW) ? 1.f : 0.f;
    const float vx1 = (x1i >= 0 && x1i < WW) ? 1.f : 0.f;
    const float vy0 = (y0  >= 0 && y0  < HH) ? 1.f : 0.f;
    const float vy1 = (y1i >= 0 && y1i < HH) ? 1.f : 0.f;

    const int x0c = min(max(x0, 0), WW-1);
    const int x1c = min(max(x1i,0), WW-1);
    const int y0c = min(max(y0, 0), HH-1);
    const int y1c = min(max(y1i,0), HH-1);

    const float w00 = (1.f-wx)*(1.f-wy)*vx0*vy0;
    const float w01 = wx*(1.f-wy)*vx1*vy0;
    const float w10 = (1.f-wx)*wy*vx0*vy1;
    const float w11 = wx*wy*vx1*vy1;

    const int i00 = y0c*WW + x0c;
    const int i01 = y0c*WW + x1c;
    const int i10 = y1c*WW + x0c;
    const int i11 = y1c*WW + x1c;
    const int o   = y*WW + x;

    const float* xb = x2 + (size_t)b*CHW;
    float* ob = g_x2w + (size_t)b*CHW;

    for (int c = threadIdx.y; c < CC; c += 8) {
        const float* p = xb + (size_t)c*HW;
        ob[(size_t)c*HW + o] = w00*p[i00] + w01*p[i01] + w10*p[i10] + w11*p[i11];
    }
}

// ---------------------------------------------------------------------------
// Kernel 2: 81-channel cost volume  out[b, dy*9+dx, y, x] =
//   lrelu( sum_c x1[b,c,y,x] * x2w[b,c,y+dy-4,x+dx-4] ),  zero padded.
// Block: (x-tile of 104, y, b).  Thread (t<234): dy = t/26, xg = t%26.
// Register tile: 4 x  x  9 dx per thread. C tiled by 16 through smem.
// ---------------------------------------------------------------------------
#define TXC 104
#define CTC 16
#define BWC 112   // 104 + 8 halo

__global__ __launch_bounds__(256)
void corr_kernel(const float* __restrict__ x1, float* __restrict__ out) {
    extern __shared__ float sm[];
    float* s_a = sm;                 // [CTC][TXC]
    float* s_b = sm + CTC*TXC;       // [9][CTC][BWC]

    const int x0t = blockIdx.x * TXC;
    const int y = blockIdx.y, b = blockIdx.z;
    const int t = threadIdx.x;
    const int dy = t / 26;
    const int xg = t - dy*26;
    const bool act = (t < 234);

    float acc[9][4];
#pragma unroll
    for (int i = 0; i < 9; i++)
#pragma unroll
        for (int j = 0; j < 4; j++) acc[i][j] = 0.f;

    const float* x1p = x1 + (size_t)b*CHW + (size_t)y*WW + x0t;
    const float* wp  = g_x2w + (size_t)b*CHW;

    for (int ct = 0; ct < CC; ct += CTC) {
        __syncthreads();
        // load x1 tile
        for (int i = t; i < CTC*TXC; i += 256) {
            int c = i / TXC, xx = i - c*TXC;
            s_a[i] = x1p[(size_t)(ct+c)*HW + xx];
        }
        // load warped-x2 halo tile: 9 rows
        for (int i = t; i < 9*CTC*BWC; i += 256) {
            int r = i / (CTC*BWC);
            int rem = i - r*(CTC*BWC);
            int c = rem / BWC, xx = rem - c*BWC;
            int gy2 = y + r - 4;
            int gx2 = x0t - 4 + xx;
            float v = 0.f;
            if ((unsigned)gy2 < HH && (unsigned)gx2 < WW)
                v = wp[(size_t)(ct+c)*HW + (size_t)gy2*WW + gx2];
            s_b[i] = v;
        }
        __syncthreads();

        if (act) {
            const float* ap = s_a + xg*4;
            const float* bp = s_b + dy*(CTC*BWC) + xg*4;
#pragma unroll
            for (int c = 0; c < CTC; c++) {
                const float a0 = ap[c*TXC+0];
                const float a1 = ap[c*TXC+1];
                const float a2 = ap[c*TXC+2];
                const float a3 = ap[c*TXC+3];
                float bv[12];
#pragma unroll
                for (int j = 0; j < 12; j += 4) {
                    float4 q = *reinterpret_cast<const float4*>(bp + c*BWC + j);
                    bv[j] = q.x; bv[j+1] = q.y; bv[j+2] = q.z; bv[j+3] = q.w;
                }
#pragma unroll
                for (int dx = 0; dx < 9; dx++) {
                    acc[dx][0] += a0*bv[dx+0];
                    acc[dx][1] += a1*bv[dx+1];
                    acc[dx][2] += a2*bv[dx+2];
                    acc[dx][3] += a3*bv[dx+3];
                }
            }
        }
    }

    if (act) {
        float* op = out + ((size_t)(b*273 + dy*9)*HH + y)*WW + x0t + xg*4;
#pragma unroll
        for (int dx = 0; dx < 9; dx++) {
            float4 v;
            v.x = lrelu(acc[dx][0]);
            v.y = lrelu(acc[dx][1]);
            v.z = lrelu(acc[dx][2]);
            v.w = lrelu(acc[dx][3]);
            *reinterpret_cast<float4*>(op + (size_t)dx*HW) = v;
        }
    }
}

// ---------------------------------------------------------------------------
// Kernel 3: 192-channel horizontal cost volume  out[b, 81+d, y, x] =
//   lrelu( sum_c x1[b,c,y,x] * r1[b,c,y,x+d-96] ),  zero padded.
// Block: (x-tile of 104, y, b).  Thread (t<312): dg = t/26 (0..11), xg = t%26.
// Register tile: 4 x  x  16 d per thread. C tiled by 32 through smem.
// ---------------------------------------------------------------------------
#define TXD 104
#define RWD 296   // 104 + 191 halo, padded to multiple of 4
#define CTD 32

__global__ __launch_bounds__(320, 2)
void disp_kernel(const float* __restrict__ x1, const float* __restrict__ r1,
                 float* __restrict__ out) {
    extern __shared__ float sm[];
    float* s_a = sm;              // [CTD][TXD]
    float* s_r = sm + CTD*TXD;    // [CTD][RWD]

    const int x0t = blockIdx.x * TXD;
    const int y = blockIdx.y, b = blockIdx.z;
    const int t = threadIdx.x;
    const int dg = t / 26;
    const int xg = t - dg*26;
    const bool act = (t < 312);

    float acc[16][4];
#pragma unroll
    for (int i = 0; i < 16; i++)
#pragma unroll
        for (int j = 0; j < 4; j++) acc[i][j] = 0.f;

    const float* x1p = x1 + (size_t)b*CHW + (size_t)y*WW + x0t;
    const float* rp  = r1 + (size_t)b*CHW + (size_t)y*WW;

    for (int ct = 0; ct < CC; ct += CTD) {
        __syncthreads();
        for (int i = t; i < CTD*TXD; i += 320) {
            int c = i / TXD, xx = i - c*TXD;
            s_a[i] = x1p[(size_t)(ct+c)*HW + xx];
        }
        for (int i = t; i < CTD*RWD; i += 320) {
            int c = i / RWD, ii = i - c*RWD;
            int gx = x0t - 96 + ii;
            float v = 0.f;
            if ((unsigned)gx < WW) v = rp[(size_t)(ct+c)*HW + gx];
            s_r[i] = v;
        }
        __syncthreads();

        if (act) {
            const float* ap = s_a + xg*4;
            const float* bp = s_r + xg*4 + dg*16;
#pragma unroll 4
            for (int c = 0; c < CTD; c++) {
                const float a0 = ap[c*TXD+0];
                const float a1 = ap[c*TXD+1];
                const float a2 = ap[c*TXD+2];
                const float a3 = ap[c*TXD+3];
                float bv[20];
#pragma unroll
                for (int j = 0; j < 20; j += 4) {
                    float4 q = *reinterpret_cast<const float4*>(bp + c*RWD + j);
                    bv[j] = q.x; bv[j+1] = q.y; bv[j+2] = q.z; bv[j+3] = q.w;
                }
#pragma unroll
                for (int dj = 0; dj < 16; dj++) {
                    acc[dj][0] += a0*bv[dj+0];
                    acc[dj][1] += a1*bv[dj+1];
                    acc[dj][2] += a2*bv[dj+2];
                    acc[dj][3] += a3*bv[dj+3];
                }
            }
        }
    }

    if (act) {
        float* op = out + ((size_t)(b*273 + 81 + dg*16)*HH + y)*WW + x0t + xg*4;
#pragma unroll
        for (int dj = 0; dj < 16; dj++) {
            float4 v;
            v.x = lrelu(acc[dj][0]);
            v.y = lrelu(acc[dj][1]);
            v.z = lrelu(acc[dj][2]);
            v.w = lrelu(acc[dj][3]);
            *reinterpret_cast<float4*>(op + (size_t)dj*HW) = v;
        }
    }
}

// ---------------------------------------------------------------------------
extern "C" void kernel_launch(void* const* d_in, const int* in_sizes, int n_in,
                              void* d_out, int out_size) {
    const float* x1   = (const float*)d_in[0];
    const float* x2   = (const float*)d_in[1];
    const float* r1   = (const float*)d_in[2];
    const float* flow = (const float*)d_in[3];
    float* out = (float*)d_out;

    const int corr_smem = (CTC*TXC + 9*CTC*BWC) * 4;   // 71168 B
    const int disp_smem = (CTD*TXD + CTD*RWD) * 4;     // 51200 B
    cudaFuncSetAttribute(corr_kernel, cudaFuncAttributeMaxDynamicSharedMemorySize, corr_smem);
    cudaFuncSetAttribute(disp_kernel, cudaFuncAttributeMaxDynamicSharedMemorySize, disp_smem);

    warp_kernel<<<dim3(WW/32, HH, BB), dim3(32, 8)>>>(x2, flow);
    corr_kernel<<<dim3(WW/TXC, HH, BB), 256, corr_smem>>>(x1, out);
    disp_kernel<<<dim3(WW/TXD, HH, BB), 320, disp_smem>>>(x1, r1, out);
}

// round 2
// speedup vs baseline: 1.1827x; 1.1827x over previous
#include <cuda_runtime.h>

#define BB 4
#define CC 64
#define HH 128
#define WW 416
#define HW (HH*WW)
#define CHW (CC*HH*WW)

// Scratch for warped x2 (no cudaMalloc allowed)
__device__ float g_x2w[(size_t)BB*CHW];

__device__ __forceinline__ float lrelu(float v) { return v >= 0.f ? v : 0.1f*v; }

// ---------------------------------------------------------------------------
// Fused kernel: blocks 0..3 in x  = 192-ch disparity cost volume (FMA-bound)
//               blocks 4..7 in x  = bilinear warp of x2 (latency-bound filler)
// The warp blocks overlap with disp blocks on the SMs, hiding the gather
// latency that made the standalone warp kernel cost 67 us.
// ---------------------------------------------------------------------------
#define TXD 104
#define RWD 296   // 104 + 191 halo, padded to multiple of 4
#define CTD 32
#define DSP_SMEM ((CTD*TXD + CTD*RWD)*4)   // 51200 B

__global__ __launch_bounds__(320, 1)
void fused_disp_warp(const float* __restrict__ x1, const float* __restrict__ r1,
                     const float* __restrict__ x2, const float* __restrict__ flow,
                     float* __restrict__ out) {
    extern __shared__ float sm[];
    const int y = blockIdx.y, b = blockIdx.z;
    const int t = threadIdx.x;

    if (blockIdx.x >= 4) {
        // ------------------ warp path ------------------
        const int x0t = (blockIdx.x - 4) * TXD;
        float* s_w = sm;                  // [4][TXD] weights
        int*   s_i = (int*)(sm + 4*TXD);  // [4][TXD] gather indices

        if (t < TXD) {
            const int x = x0t + t;
            const float fx = flow[((size_t)(b*2+0)*HH + y)*WW + x];
            const float fy = flow[((size_t)(b*2+1)*HH + y)*WW + x];
            const float gx = (float)x + fx;
            const float gy = (float)y + fy;
            const float x0f = floorf(gx), y0f = floorf(gy);
            const float wx = gx - x0f, wy = gy - y0f;
            const int x0 = (int)x0f, y0 = (int)y0f;
            const int x1i = x0 + 1,  y1i = y0 + 1;

            const float vx0 = (x0  >= 0 && x0  < WW) ? 1.f : 0.f;
            const float vx1 = (x1i >= 0 && x1i < WW) ? 1.f : 0.f;
            const float vy0 = (y0  >= 0 && y0  < HH) ? 1.f : 0.f;
            const float vy1 = (y1i >= 0 && y1i < HH) ? 1.f : 0.f;

            const int x0c = min(max(x0, 0), WW-1);
            const int x1c = min(max(x1i,0), WW-1);
            const int y0c = min(max(y0, 0), HH-1);
            const int y1c = min(max(y1i,0), HH-1);

            s_w[0*TXD+t] = (1.f-wx)*(1.f-wy)*vx0*vy0;
            s_w[1*TXD+t] = wx*(1.f-wy)*vx1*vy0;
            s_w[2*TXD+t] = (1.f-wx)*wy*vx0*vy1;
            s_w[3*TXD+t] = wx*wy*vx1*vy1;
            s_i[0*TXD+t] = y0c*WW + x0c;
            s_i[1*TXD+t] = y0c*WW + x1c;
            s_i[2*TXD+t] = y1c*WW + x0c;
            s_i[3*TXD+t] = y1c*WW + x1c;
        }
        __syncthreads();

        const float* xb = x2 + (size_t)b*CHW;
        float* ob = g_x2w + (size_t)b*CHW + (size_t)y*WW + x0t;
        for (int e = t; e < TXD*CC; e += 320) {
            const int c = e / TXD, xi = e - c*TXD;
            const float w00 = s_w[0*TXD+xi], w01 = s_w[1*TXD+xi];
            const float w10 = s_w[2*TXD+xi], w11 = s_w[3*TXD+xi];
            const int i00 = s_i[0*TXD+xi], i01 = s_i[1*TXD+xi];
            const int i10 = s_i[2*TXD+xi], i11 = s_i[3*TXD+xi];
            const float* p = xb + (size_t)c*HW;
            ob[(size_t)c*HW + xi] = w00*__ldg(p+i00) + w01*__ldg(p+i01)
                                  + w10*__ldg(p+i10) + w11*__ldg(p+i11);
        }
        return;
    }

    // ------------------ disparity path ------------------
    float* s_a = sm;              // [CTD][TXD]
    float* s_r = sm + CTD*TXD;    // [CTD][RWD]

    const int x0t = blockIdx.x * TXD;
    const int dg = t / 26;
    const int xg = t - dg*26;
    const bool act = (t < 312);

    float acc[16][4];
#pragma unroll
    for (int i = 0; i < 16; i++)
#pragma unroll
        for (int j = 0; j < 4; j++) acc[i][j] = 0.f;

    const float* x1p = x1 + (size_t)b*CHW + (size_t)y*WW + x0t;
    const float* rp  = r1 + (size_t)b*CHW + (size_t)y*WW;

    for (int ct = 0; ct < CC; ct += CTD) {
        __syncthreads();
        for (int i = t; i < CTD*TXD; i += 320) {
            int c = i / TXD, xx = i - c*TXD;
            s_a[i] = x1p[(size_t)(ct+c)*HW + xx];
        }
        for (int i = t; i < CTD*RWD; i += 320) {
            int c = i / RWD, ii = i - c*RWD;
            int gx = x0t - 96 + ii;
            float v = 0.f;
            if ((unsigned)gx < WW) v = rp[(size_t)(ct+c)*HW + gx];
            s_r[i] = v;
        }
        __syncthreads();

        if (act) {
            const float* ap = s_a + xg*4;
            const float* bp = s_r + xg*4 + dg*16;
#pragma unroll 4
            for (int c = 0; c < CTD; c++) {
                const float a0 = ap[c*TXD+0];
                const float a1 = ap[c*TXD+1];
                const float a2 = ap[c*TXD+2];
                const float a3 = ap[c*TXD+3];
                float bv[20];
#pragma unroll
                for (int j = 0; j < 20; j += 4) {
                    float4 q = *reinterpret_cast<const float4*>(bp + c*RWD + j);
                    bv[j] = q.x; bv[j+1] = q.y; bv[j+2] = q.z; bv[j+3] = q.w;
                }
#pragma unroll
                for (int dj = 0; dj < 16; dj++) {
                    acc[dj][0] += a0*bv[dj+0];
                    acc[dj][1] += a1*bv[dj+1];
                    acc[dj][2] += a2*bv[dj+2];
                    acc[dj][3] += a3*bv[dj+3];
                }
            }
        }
    }

    if (act) {
        float* op = out + ((size_t)(b*273 + 81 + dg*16)*HH + y)*WW + x0t + xg*4;
#pragma unroll
        for (int dj = 0; dj < 16; dj++) {
            float4 v;
            v.x = lrelu(acc[dj][0]);
            v.y = lrelu(acc[dj][1]);
            v.z = lrelu(acc[dj][2]);
            v.w = lrelu(acc[dj][3]);
            *reinterpret_cast<float4*>(op + (size_t)dj*HW) = v;
        }
    }
}

// ---------------------------------------------------------------------------
// 81-channel cost volume  out[b, dy*9+dx, y, x] =
//   lrelu( sum_c x1[b,c,y,x] * x2w[b,c,y+dy-4,x+dx-4] ),  zero padded.
// ---------------------------------------------------------------------------
#define TXC 104
#define CTC 16
#define BWC 112   // 104 + 8 halo

__global__ __launch_bounds__(256)
void corr_kernel(const float* __restrict__ x1, float* __restrict__ out) {
    extern __shared__ float sm[];
    float* s_a = sm;                 // [CTC][TXC]
    float* s_b = sm + CTC*TXC;       // [9][CTC][BWC]

    const int x0t = blockIdx.x * TXC;
    const int y = blockIdx.y, b = blockIdx.z;
    const int t = threadIdx.x;
    const int dy = t / 26;
    const int xg = t - dy*26;
    const bool act = (t < 234);

    float acc[9][4];
#pragma unroll
    for (int i = 0; i < 9; i++)
#pragma unroll
        for (int j = 0; j < 4; j++) acc[i][j] = 0.f;

    const float* x1p = x1 + (size_t)b*CHW + (size_t)y*WW + x0t;
    const float* wp  = g_x2w + (size_t)b*CHW;

    for (int ct = 0; ct < CC; ct += CTC) {
        __syncthreads();
        for (int i = t; i < CTC*TXC; i += 256) {
            int c = i / TXC, xx = i - c*TXC;
            s_a[i] = x1p[(size_t)(ct+c)*HW + xx];
        }
        for (int i = t; i < 9*CTC*BWC; i += 256) {
            int r = i / (CTC*BWC);
            int rem = i - r*(CTC*BWC);
            int c = rem / BWC, xx = rem - c*BWC;
            int gy2 = y + r - 4;
            int gx2 = x0t - 4 + xx;
            float v = 0.f;
            if ((unsigned)gy2 < HH && (unsigned)gx2 < WW)
                v = wp[(size_t)(ct+c)*HW + (size_t)gy2*WW + gx2];
            s_b[i] = v;
        }
        __syncthreads();

        if (act) {
            const float* ap = s_a + xg*4;
            const float* bp = s_b + dy*(CTC*BWC) + xg*4;
#pragma unroll
            for (int c = 0; c < CTC; c++) {
                const float a0 = ap[c*TXC+0];
                const float a1 = ap[c*TXC+1];
                const float a2 = ap[c*TXC+2];
                const float a3 = ap[c*TXC+3];
                float bv[12];
#pragma unroll
                for (int j = 0; j < 12; j += 4) {
                    float4 q = *reinterpret_cast<const float4*>(bp + c*BWC + j);
                    bv[j] = q.x; bv[j+1] = q.y; bv[j+2] = q.z; bv[j+3] = q.w;
                }
#pragma unroll
                for (int dx = 0; dx < 9; dx++) {
                    acc[dx][0] += a0*bv[dx+0];
                    acc[dx][1] += a1*bv[dx+1];
                    acc[dx][2] += a2*bv[dx+2];
                    acc[dx][3] += a3*bv[dx+3];
                }
            }
        }
    }

    if (act) {
        float* op = out + ((size_t)(b*273 + dy*9)*HH + y)*WW + x0t + xg*4;
#pragma unroll
        for (int dx = 0; dx < 9; dx++) {
            float4 v;
            v.x = lrelu(acc[dx][0]);
            v.y = lrelu(acc[dx][1]);
            v.z = lrelu(acc[dx][2]);
            v.w = lrelu(acc[dx][3]);
            *reinterpret_cast<float4*>(op + (size_t)dx*HW) = v;
        }
    }
}

// ---------------------------------------------------------------------------
extern "C" void kernel_launch(void* const* d_in, const int* in_sizes, int n_in,
                              void* d_out, int out_size) {
    const float* x1   = (const float*)d_in[0];
    const float* x2   = (const float*)d_in[1];
    const float* r1   = (const float*)d_in[2];
    const float* flow = (const float*)d_in[3];
    float* out = (float*)d_out;

    const int corr_smem = (CTC*TXC + 9*CTC*BWC) * 4;   // 71168 B
    cudaFuncSetAttribute(fused_disp_warp, cudaFuncAttributeMaxDynamicSharedMemorySize, DSP_SMEM);
    cudaFuncSetAttribute(corr_kernel, cudaFuncAttributeMaxDynamicSharedMemorySize, corr_smem);

    fused_disp_warp<<<dim3(8, HH, BB), 320, DSP_SMEM>>>(x1, r1, x2, flow, out);
    corr_kernel<<<dim3(WW/TXC, HH, BB), 256, corr_smem>>>(x1, out);
}

// round 4
// speedup vs baseline: 2.0779x; 1.7570x over previous
#include <cuda_runtime.h>
#include <cuda_pipeline.h>

#define BB 4
#define CC 64
#define HH 128
#define WW 416
#define HW (HH*WW)
#define CHW (CC*HH*WW)

// Scratch for warped x2 (no cudaMalloc allowed)
__device__ float g_x2w[(size_t)BB*CHW];

__device__ __forceinline__ float lrelu(float v) { return v >= 0.f ? v : 0.1f*v; }

// ===========================================================================
// Fused kernel: blocks 0..3 in x = 192-ch disparity cost volume (FMA-bound)
//               blocks 4..7 in x = bilinear warp of x2 (latency-bound filler)
// ===========================================================================
#define TXD 104
#define RWD 296                         // 104 + 191 halo, padded to mult of 4
#define CTD 16
#define NTD (CC/CTD)                    // 4 pipeline stages
#define DISP_BUF (CTD*TXD + CTD*RWD)    // 6400 floats per buffer
#define DSP_SMEM (2*DISP_BUF*4)         // 51200 B

__global__ __launch_bounds__(320)
void fused_disp_warp(const float* __restrict__ x1, const float* __restrict__ r1,
                     const float* __restrict__ x2, const float* __restrict__ flow,
                     float* __restrict__ out) {
    extern __shared__ float sm[];
    const int y = blockIdx.y, b = blockIdx.z;
    const int t = threadIdx.x;

    if (blockIdx.x >= 4) {
        // ------------------ warp path ------------------
        const int x0t = (blockIdx.x - 4) * TXD;
        float* s_w = sm;                  // [4][TXD] weights
        int*   s_i = (int*)(sm + 4*TXD);  // [4][TXD] gather indices

        if (t < TXD) {
            const int x = x0t + t;
            const float fx = flow[((size_t)(b*2+0)*HH + y)*WW + x];
            const float fy = flow[((size_t)(b*2+1)*HH + y)*WW + x];
            const float gx = (float)x + fx;
            const float gy = (float)y + fy;
            const float x0f = floorf(gx), y0f = floorf(gy);
            const float wx = gx - x0f, wy = gy - y0f;
            const int x0 = (int)x0f, y0 = (int)y0f;
            const int x1i = x0 + 1,  y1i = y0 + 1;

            const float vx0 = (x0  >= 0 && x0  < WW) ? 1.f : 0.f;
            const float vx1 = (x1i >= 0 && x1i < WW) ? 1.f : 0.f;
            const float vy0 = (y0  >= 0 && y0  < HH) ? 1.f : 0.f;
            const float vy1 = (y1i >= 0 && y1i < HH) ? 1.f : 0.f;

            const int x0c = min(max(x0, 0), WW-1);
            const int x1c = min(max(x1i,0), WW-1);
            const int y0c = min(max(y0, 0), HH-1);
            const int y1c = min(max(y1i,0), HH-1);

            s_w[0*TXD+t] = (1.f-wx)*(1.f-wy)*vx0*vy0;
            s_w[1*TXD+t] = wx*(1.f-wy)*vx1*vy0;
            s_w[2*TXD+t] = (1.f-wx)*wy*vx0*vy1;
            s_w[3*TXD+t] = wx*wy*vx1*vy1;
            s_i[0*TXD+t] = y0c*WW + x0c;
            s_i[1*TXD+t] = y0c*WW + x1c;
            s_i[2*TXD+t] = y1c*WW + x0c;
            s_i[3*TXD+t] = y1c*WW + x1c;
        }
        __syncthreads();

        const float* xb = x2 + (size_t)b*CHW;
        float* ob = g_x2w + (size_t)b*CHW + (size_t)y*WW + x0t;
        for (int e = t; e < TXD*CC; e += 320) {
            const int c = e / TXD, xi = e - c*TXD;
            const float w00 = s_w[0*TXD+xi], w01 = s_w[1*TXD+xi];
            const float w10 = s_w[2*TXD+xi], w11 = s_w[3*TXD+xi];
            const int i00 = s_i[0*TXD+xi], i01 = s_i[1*TXD+xi];
            const int i10 = s_i[2*TXD+xi], i11 = s_i[3*TXD+xi];
            const float* p = xb + (size_t)c*HW;
            ob[(size_t)c*HW + xi] = w00*__ldg(p+i00) + w01*__ldg(p+i01)
                                  + w10*__ldg(p+i10) + w11*__ldg(p+i11);
        }
        return;
    }

    // ------------------ disparity path ------------------
    const int x0t = blockIdx.x * TXD;
    const int dg = t / 26;
    const int xg = t - dg*26;
    const bool act = (t < 312);

    const float* x1p = x1 + (size_t)b*CHW + (size_t)y*WW + x0t;
    const float* rp  = r1 + (size_t)b*CHW + (size_t)y*WW;

    float acc[16][4];
#pragma unroll
    for (int i = 0; i < 16; i++)
#pragma unroll
        for (int j = 0; j < 4; j++) acc[i][j] = 0.f;

    // ---- async tile loader (all-float4; boundary f4s are all-in or all-out)
    auto load_tile = [&](int bi, int kt) {
        float* da = sm + bi*DISP_BUF;
        float* dr = da + CTD*TXD;
        const int ct = kt * CTD;
        // s_a: CTD rows of 26 f4 = 416 f4
#pragma unroll
        for (int i = t; i < CTD*26; i += 320) {
            int c = i / 26, x4 = (i - 26*c) * 4;
            __pipeline_memcpy_async(da + c*TXD + x4,
                                    x1p + (size_t)(ct+c)*HW + x4, 16);
        }
        // s_r: CTD rows of 74 f4 = 1184 f4
#pragma unroll
        for (int i = t; i < CTD*74; i += 320) {
            int c = i / 74, x4 = (i - 74*c) * 4;
            int gx = x0t - 96 + x4;
            float* dst = dr + c*RWD + x4;
            if ((unsigned)gx < WW)
                __pipeline_memcpy_async(dst, rp + (size_t)(ct+c)*HW + gx, 16);
            else
                *reinterpret_cast<float4*>(dst) = make_float4(0.f,0.f,0.f,0.f);
        }
    };

    load_tile(0, 0);
    __pipeline_commit();

    for (int k = 0; k < NTD; k++) {
        if (k + 1 < NTD) {
            load_tile((k+1) & 1, k+1);
            __pipeline_commit();
            __pipeline_wait_prior(1);
        } else {
            __pipeline_wait_prior(0);
        }
        __syncthreads();

        if (act) {
            const float* da = sm + (k&1)*DISP_BUF;
            const float* ap = da + xg*4;
            const float* bp = da + CTD*TXD + xg*4 + dg*16;
#pragma unroll 4
            for (int c = 0; c < CTD; c++) {
                const float4 a  = *reinterpret_cast<const float4*>(ap + c*TXD);
                const float4 q0 = *reinterpret_cast<const float4*>(bp + c*RWD);
                const float4 q1 = *reinterpret_cast<const float4*>(bp + c*RWD + 4);
                const float4 q2 = *reinterpret_cast<const float4*>(bp + c*RWD + 8);
                const float4 q3 = *reinterpret_cast<const float4*>(bp + c*RWD + 12);
                const float4 q4 = *reinterpret_cast<const float4*>(bp + c*RWD + 16);
                const float bv[20] = {q0.x,q0.y,q0.z,q0.w, q1.x,q1.y,q1.z,q1.w,
                                      q2.x,q2.y,q2.z,q2.w, q3.x,q3.y,q3.z,q3.w,
                                      q4.x,q4.y,q4.z,q4.w};
#pragma unroll
                for (int dj = 0; dj < 16; dj++) {
                    acc[dj][0] += a.x*bv[dj+0];
                    acc[dj][1] += a.y*bv[dj+1];
                    acc[dj][2] += a.z*bv[dj+2];
                    acc[dj][3] += a.w*bv[dj+3];
                }
            }
        }
        __syncthreads();
    }

    if (act) {
        float* op = out + ((size_t)(b*273 + 81 + dg*16)*HH + y)*WW + x0t + xg*4;
#pragma unroll
        for (int dj = 0; dj < 16; dj++) {
            float4 v;
            v.x = lrelu(acc[dj][0]);
            v.y = lrelu(acc[dj][1]);
            v.z = lrelu(acc[dj][2]);
            v.w = lrelu(acc[dj][3]);
            *reinterpret_cast<float4*>(op + (size_t)dj*HW) = v;
        }
    }
}

// ===========================================================================
// 81-channel cost volume  out[b, dy*9+dx, y, x] =
//   lrelu( sum_c x1[b,c,y,x] * x2w[b,c,y+dy-4,x+dx-4] ),  zero padded.
// ===========================================================================
#define TXC 104
#define CTC 8
#define BWC 112                          // 104 + 8 halo
#define NTC (CC/CTC)                     // 8 pipeline stages
#define CORR_BUF (CTC*TXC + 9*CTC*BWC)   // 8896 floats per buffer
#define CORR_SMEM (2*CORR_BUF*4)         // 71168 B

__global__ __launch_bounds__(256)
void corr_kernel(const float* __restrict__ x1, float* __restrict__ out) {
    extern __shared__ float sm[];

    const int x0t = blockIdx.x * TXC;
    const int y = blockIdx.y, b = blockIdx.z;
    const int t = threadIdx.x;
    const int dy = t / 26;
    const int xg = t - dy*26;
    const bool act = (t < 234);

    const float* x1p = x1 + (size_t)b*CHW + (size_t)y*WW + x0t;
    const float* wp  = g_x2w + (size_t)b*CHW;

    // per-thread load indices, hoisted out of the stage loop
    const int ca = t / 26, xa = (t - 26*ca) * 4;          // s_a: 208 f4, t<208
    const int cb = t / 28, xb4 = (t - 28*cb) * 4;         // s_b: 224 f4 per row
    const int gx2 = x0t - 4 + xb4;
    const bool px = ((unsigned)gx2 < WW);

    float acc[9][4];
#pragma unroll
    for (int i = 0; i < 9; i++)
#pragma unroll
        for (int j = 0; j < 4; j++) acc[i][j] = 0.f;

    auto load_tile = [&](int bi, int kt) {
        float* da = sm + bi*CORR_BUF;
        float* db = da + CTC*TXC;
        const int ct = kt * CTC;
        if (t < 208)
            __pipeline_memcpy_async(da + ca*TXC + xa,
                                    x1p + (size_t)(ct+ca)*HW + xa, 16);
        if (t < 224) {
            const float* srcb = wp + (size_t)(ct+cb)*HW + gx2;
            float* dstb = db + cb*BWC + xb4;
#pragma unroll
            for (int r = 0; r < 9; r++) {
                const int gy2 = y + r - 4;
                if (px && (unsigned)gy2 < HH)
                    __pipeline_memcpy_async(dstb + r*(CTC*BWC), srcb + gy2*WW, 16);
                else
                    *reinterpret_cast<float4*>(dstb + r*(CTC*BWC)) =
                        make_float4(0.f,0.f,0.f,0.f);
            }
        }
    };

    load_tile(0, 0);
    __pipeline_commit();

    for (int k = 0; k < NTC; k++) {
        if (k + 1 < NTC) {
            load_tile((k+1) & 1, k+1);
            __pipeline_commit();
            __pipeline_wait_prior(1);
        } else {
            __pipeline_wait_prior(0);
        }
        __syncthreads();

        if (act) {
            const float* da = sm + (k&1)*CORR_BUF;
            const float* ap = da + xg*4;
            const float* bp = da + CTC*TXC + dy*(CTC*BWC) + xg*4;
#pragma unroll
            for (int c = 0; c < CTC; c++) {
                const float4 a  = *reinterpret_cast<const float4*>(ap + c*TXC);
                const float4 q0 = *reinterpret_cast<const float4*>(bp + c*BWC);
                const float4 q1 = *reinterpret_cast<const float4*>(bp + c*BWC + 4);
                const float4 q2 = *reinterpret_cast<const float4*>(bp + c*BWC + 8);
                const float bv[12] = {q0.x,q0.y,q0.z,q0.w, q1.x,q1.y,q1.z,q1.w,
                                      q2.x,q2.y,q2.z,q2.w};
#pragma unroll
                for (int dx = 0; dx < 9; dx++) {
                    acc[dx][0] += a.x*bv[dx+0];
                    acc[dx][1] += a.y*bv[dx+1];
                    acc[dx][2] += a.z*bv[dx+2];
                    acc[dx][3] += a.w*bv[dx+3];
                }
            }
        }
        __syncthreads();
    }

    if (act) {
        float* op = out + ((size_t)(b*273 + dy*9)*HH + y)*WW + x0t + xg*4;
#pragma unroll
        for (int dx = 0; dx < 9; dx++) {
            float4 v;
            v.x = lrelu(acc[dx][0]);
            v.y = lrelu(acc[dx][1]);
            v.z = lrelu(acc[dx][2]);
            v.w = lrelu(acc[dx][3]);
            *reinterpret_cast<float4*>(op + (size_t)dx*HW) = v;
        }
    }
}

// ===========================================================================
extern "C" void kernel_launch(void* const* d_in, const int* in_sizes, int n_in,
                              void* d_out, int out_size) {
    const float* x1   = (const float*)d_in[0];
    const float* x2   = (const float*)d_in[1];
    const float* r1   = (const float*)d_in[2];
    const float* flow = (const float*)d_in[3];
    float* out = (float*)d_out;

    cudaFuncSetAttribute(fused_disp_warp, cudaFuncAttributeMaxDynamicSharedMemorySize, DSP_SMEM);
    cudaFuncSetAttribute(corr_kernel, cudaFuncAttributeMaxDynamicSharedMemorySize, CORR_SMEM);

    fused_disp_warp<<<dim3(8, HH, BB), 320, DSP_SMEM>>>(x1, r1, x2, flow, out);
    corr_kernel<<<dim3(WW/TXC, HH, BB), 256, CORR_SMEM>>>(x1, out);
}